// round 1
// baseline (speedup 1.0000x reference)
#include <cuda_runtime.h>

// out[i] = x[i] - max(ceil(x[i]), 1.0f)
// Pure streaming elementwise kernel: 128-bit vectorized, grid-stride.

__device__ __forceinline__ float f(float v) {
    return v - fmaxf(ceilf(v), 1.0f);
}

__global__ void __launch_bounds__(256)
recur_kernel_vec4(const float4* __restrict__ x, float4* __restrict__ out, long n4) {
    long i = (long)blockIdx.x * blockDim.x + threadIdx.x;
    long stride = (long)gridDim.x * blockDim.x;
    for (; i < n4; i += stride) {
        float4 v = x[i];
        float4 r;
        r.x = f(v.x);
        r.y = f(v.y);
        r.z = f(v.z);
        r.w = f(v.w);
        out[i] = r;
    }
}

__global__ void recur_kernel_tail(const float* __restrict__ x, float* __restrict__ out,
                                  long start, long n) {
    long i = start + (long)blockIdx.x * blockDim.x + threadIdx.x;
    if (i < n) out[i] = f(x[i]);
}

extern "C" void kernel_launch(void* const* d_in, const int* in_sizes, int n_in,
                              void* d_out, int out_size) {
    const float* x = (const float*)d_in[0];
    float* out = (float*)d_out;
    long n = (long)in_sizes[0];

    long n4 = n / 4;
    if (n4 > 0) {
        int threads = 256;
        // Enough blocks to cover n4 once with a few iterations per thread;
        // cap grid so each thread does >= 4 vec4 iterations (keeps MLP high).
        long want = (n4 + threads - 1) / threads;
        long maxBlocks = 148L * 8;  // 8 CTAs/SM worth of wave-1 parallelism
        // Use grid-stride with a moderate grid: ~2 elements of work batching.
        int blocks = (int)((want < maxBlocks) ? want : maxBlocks);
        recur_kernel_vec4<<<blocks, threads>>>((const float4*)x, (float4*)out, n4);
    }
    long rem_start = n4 * 4;
    long rem = n - rem_start;
    if (rem > 0) {
        int threads = 256;
        int blocks = (int)((rem + threads - 1) / threads);
        recur_kernel_tail<<<blocks, threads>>>(x, out, rem_start, n);
    }
}